// round 17
// baseline (speedup 1.0000x reference)
#include <cuda_runtime.h>
#include <cuda_fp16.h>
#include <math.h>
#include <stdint.h>

#define BB 2
#define SS 2048
#define DD 1024
#define HH 16
#define DK 64
#define MROWS (BB*SS)   // 4096

// Scratch (device globals — allocation is forbidden)
__device__ float g_cos[SS*32];
__device__ float g_sin[SS*32];
// fp16 packed operands for flash: u32 = packed half2
__device__ uint32_t g_qh[BB*HH*SS*32];    // Q fp16 hi
__device__ uint32_t g_ql[BB*HH*SS*32];    // Q fp16 lo (exact residual)
__device__ uint32_t g_kh[BB*HH*SS*32];    // K fp16 (single)
__device__ uint32_t g_v16[BB*HH*SS*32];   // V fp16 [bh][s][k2] (pre-pairing)
__device__ uint32_t g_vh[BB*HH*(SS/2)*DK];// V fp16 key-pair packed
// fp16-split GEMM operands, CHUNK-MAJOR blocked: [chunk64][rows][8 u32]
__device__ uint32_t g_ah[3][MROWS*512];   // activation fp16 hi
__device__ uint32_t g_al[3][MROWS*512];   // activation fp16 lo
__device__ uint32_t g_wh[4][DD*512];      // weight fp16 (single)
__device__ uint32_t g_cth[MROWS*512];     // ctx fp16 hi
__device__ uint32_t g_ctl[MROWS*512];     // ctx fp16 lo

// ---------------------------------------------------------------------------
__device__ __forceinline__ uint32_t pack_hi16(float a, float b, float& ra, float& rb)
{
    __half ha = __float2half_rn(a);
    __half hb = __float2half_rn(b);
    ra = a - __half2float(ha);
    rb = b - __half2float(hb);
    __half2 p; p.x = ha; p.y = hb;
    return *reinterpret_cast<uint32_t*>(&p);
}
__device__ __forceinline__ uint32_t pack_lo16(float ra, float rb)
{
    __half2 p = __floats2half2_rn(ra, rb);
    return *reinterpret_cast<uint32_t*>(&p);
}
__device__ __forceinline__ uint32_t pack16(float a, float b)
{
    __half2 p = __floats2half2_rn(a, b);
    return *reinterpret_cast<uint32_t*>(&p);
}
__device__ __forceinline__ float ex2(float x)
{
    float r;
    asm("ex2.approx.f32 %0, %1;" : "=f"(r) : "f"(x));
    return r;
}

#define MMA_F16(d, a, b) \
    asm volatile("mma.sync.aligned.m16n8k16.row.col.f32.f16.f16.f32 " \
        "{%0,%1,%2,%3}, {%4,%5,%6,%7}, {%8,%9}, {%0,%1,%2,%3};" \
        : "+f"(d[0]), "+f"(d[1]), "+f"(d[2]), "+f"(d[3]) \
        : "r"(a[0]), "r"(a[1]), "r"(a[2]), "r"(a[3]), "r"(b[0]), "r"(b[1]))

#define CPA16(dst, src)  asm volatile("cp.async.cg.shared.global [%0], [%1], 16;" :: "r"(dst), "l"(src))
#define CPA_COMMIT()     asm volatile("cp.async.commit_group;" ::: "memory")
#define CPA_WAIT(N)      asm volatile("cp.async.wait_group %0;" :: "n"(N) : "memory")

// ---------------------------------------------------------------------------
__global__ __launch_bounds__(256) void rope_tables(float* cosT, float* sinT)
{
    const int t = blockIdx.x * 256 + threadIdx.x;
    const int j = t & 31;
    const int s = t >> 5;
    double inv = exp(-(double)j * 0.28782313662425575);
    double sd, cd;
    sincos((double)s * inv, &sd, &cd);
    cosT[t] = (float)cd;
    sinT[t] = (float)sd;
}

// ---------------------------------------------------------------------------
// Activations: fp16 hi+lo, chunk-major blocked.
// ---------------------------------------------------------------------------
__global__ __launch_bounds__(256) void split_act3(
    const float* __restrict__ X0, const float* __restrict__ X1,
    const float* __restrict__ X2,
    uint32_t* __restrict__ Xh, uint32_t* __restrict__ Xl, size_t ostride)
{
    const float* X = (blockIdx.y == 0) ? X0 : ((blockIdx.y == 1) ? X1 : X2);
    uint32_t* H = Xh + blockIdx.y * ostride;
    uint32_t* L = Xl + blockIdx.y * ostride;
    const size_t t = (size_t)blockIdx.x * 256 + threadIdx.x;
    const int row   = (int)(t >> 7);
    const int rem   = (int)(t & 127);
    const int chunk = rem >> 1;
    const int half  = rem & 1;
    float4 v0 = ((const float4*)X)[2*t];
    float4 v1 = ((const float4*)X)[2*t+1];
    float r0, r1, r2, r3, r4, r5, r6, r7;
    uint4 h, l;
    h.x = pack_hi16(v0.x, v0.y, r0, r1);
    h.y = pack_hi16(v0.z, v0.w, r2, r3);
    h.z = pack_hi16(v1.x, v1.y, r4, r5);
    h.w = pack_hi16(v1.z, v1.w, r6, r7);
    l.x = pack_lo16(r0, r1); l.y = pack_lo16(r2, r3);
    l.z = pack_lo16(r4, r5); l.w = pack_lo16(r6, r7);
    const size_t d = ((size_t)chunk * MROWS + row) * 2 + half;
    ((uint4*)H)[d] = h;
    ((uint4*)L)[d] = l;
}

// Weights: fp16 single, chunk-major blocked.
__global__ __launch_bounds__(256) void split_w4(
    const float* __restrict__ X0, const float* __restrict__ X1,
    const float* __restrict__ X2, const float* __restrict__ X3,
    uint32_t* __restrict__ Xh, size_t ostride)
{
    const float* X = (blockIdx.y == 0) ? X0 : ((blockIdx.y == 1) ? X1 :
                     ((blockIdx.y == 2) ? X2 : X3));
    uint32_t* H = Xh + blockIdx.y * ostride;
    const size_t t = (size_t)blockIdx.x * 256 + threadIdx.x;
    const int row   = (int)(t >> 7);
    const int rem   = (int)(t & 127);
    const int chunk = rem >> 1;
    const int half  = rem & 1;
    float4 v0 = ((const float4*)X)[2*t];
    float4 v1 = ((const float4*)X)[2*t+1];
    uint4 h;
    h.x = pack16(v0.x, v0.y);
    h.y = pack16(v0.z, v0.w);
    h.z = pack16(v1.x, v1.y);
    h.w = pack16(v1.z, v1.w);
    const size_t d = ((size_t)chunk * DD + row) * 2 + half;
    ((uint4*)H)[d] = h;
}

// ---------------------------------------------------------------------------
// gemm_fp16b: 2-pass fp16 GEMM, BK=32, 32x64 warp tiles, pitch-20 smem.
// Fused epilogues by mode: 0 = fp32 C (Wo); 1 = RoPE+scale -> qh/ql fp16 hi/lo;
// 2 = RoPE -> kh fp16; 3 = fp16 pack -> v16 [bh][s][k2].
// Each warp's 64 output columns are exactly one head (wn in {0,64}).
// ---------------------------------------------------------------------------
#define GP2 20
#define GA  (128*GP2)
#define GSTG2 (3*GA)
#define GEMM_SMEM (2*GSTG2*4)
#define ACH 32768
#define WCH 8192

struct GArg {
    const uint32_t *ah, *al, *wh;
    const float* bias;
    float* c;
    uint32_t *o1, *o2;
    int mode;
};

__global__ __launch_bounds__(256, 2) void gemm_fp16b(
    GArg g0, GArg g1, GArg g2,
    const float* __restrict__ cosT, const float* __restrict__ sinT)
{
    extern __shared__ uint32_t gsm[];
    GArg g = (blockIdx.z == 0) ? g0 : ((blockIdx.z == 1) ? g1 : g2);

    const int tid = threadIdx.x;
    const int bm = blockIdx.y, bn = blockIdx.x;
    const int lane = tid & 31, wid = tid >> 5;
    const int wm = (wid & 3) * 32;
    const int wn = (wid >> 2) * 64;
    const int qrow = lane >> 2, qk = lane & 3;

    const int r = tid >> 1;
    const int x = tid & 1;

    const uint32_t* AhG = g.ah + (size_t)(bm*128 + r)*8 + 4*x;
    const uint32_t* AlG = g.al + (size_t)(bm*128 + r)*8 + 4*x;
    const uint32_t* WhG = g.wh + (size_t)(bn*128 + r)*8 + 4*x;
    const int dA = r*GP2 + 4*x;

    float d[2][8][4];
    #pragma unroll
    for (int mt = 0; mt < 2; mt++)
        #pragma unroll
        for (int nt = 0; nt < 8; nt++)
            #pragma unroll
            for (int i = 0; i < 4; i++) d[mt][nt][i] = 0.f;

    {
        uint4 a0 = *(const uint4*)(AhG);
        uint4 a1 = *(const uint4*)(AhG + ACH);
        uint4 b0 = *(const uint4*)(AlG);
        uint4 b1 = *(const uint4*)(AlG + ACH);
        uint4 c0 = *(const uint4*)(WhG);
        uint4 c1 = *(const uint4*)(WhG + WCH);
        *(uint4*)&gsm[dA]          = a0;  *(uint4*)&gsm[dA + 8]          = a1;
        *(uint4*)&gsm[GA + dA]     = b0;  *(uint4*)&gsm[GA + dA + 8]     = b1;
        *(uint4*)&gsm[2*GA + dA]   = c0;  *(uint4*)&gsm[2*GA + dA + 8]   = c1;
    }
    __syncthreads();

    int st = 0;
    for (int c = 1; c <= 32; c++) {
        uint4 na0, na1, nb0, nb1, nc0, nc1;
        const bool has = (c < 32);
        if (has) {
            na0 = *(const uint4*)(AhG + (size_t)(2*c)*ACH);
            na1 = *(const uint4*)(AhG + (size_t)(2*c+1)*ACH);
            nb0 = *(const uint4*)(AlG + (size_t)(2*c)*ACH);
            nb1 = *(const uint4*)(AlG + (size_t)(2*c+1)*ACH);
            nc0 = *(const uint4*)(WhG + (size_t)(2*c)*WCH);
            nc1 = *(const uint4*)(WhG + (size_t)(2*c+1)*WCH);
        }

        const uint32_t* S = gsm + st*GSTG2;

        #pragma unroll
        for (int kk = 0; kk < 2; kk++) {
            uint32_t afh[2][4], afl[2][4], bfh[8][2];
            #pragma unroll
            for (int mt = 0; mt < 2; mt++) {
                const int m0 = wm + mt*16 + qrow;
                #pragma unroll
                for (int i = 0; i < 4; i++) {
                    const int m  = m0 + ((i & 1) << 3);
                    const int k2 = qk + ((i >> 1) << 2) + 8*kk;
                    afh[mt][i] = S[m*GP2 + k2];
                    afl[mt][i] = S[GA + m*GP2 + k2];
                }
            }
            #pragma unroll
            for (int nt = 0; nt < 8; nt++) {
                const int n0 = wn + nt*8 + qrow;
                #pragma unroll
                for (int i = 0; i < 2; i++)
                    bfh[nt][i] = S[2*GA + n0*GP2 + qk + 4*i + 8*kk];
            }
            #pragma unroll
            for (int mt = 0; mt < 2; mt++)
                #pragma unroll
                for (int nt = 0; nt < 8; nt++) {
                    MMA_F16(d[mt][nt], afh[mt], bfh[nt]);
                    MMA_F16(d[mt][nt], afl[mt], bfh[nt]);
                }
        }

        if (has) {
            uint32_t* T = gsm + (st ^ 1)*GSTG2;
            *(uint4*)&T[dA]        = na0;  *(uint4*)&T[dA + 8]        = na1;
            *(uint4*)&T[GA + dA]   = nb0;  *(uint4*)&T[GA + dA + 8]   = nb1;
            *(uint4*)&T[2*GA + dA] = nc0;  *(uint4*)&T[2*GA + dA + 8] = nc1;
        }
        __syncthreads();
        st ^= 1;
    }

    // ---- epilogue ----
    if (g.mode == 0) {
        #pragma unroll
        for (int mt = 0; mt < 2; mt++)
            #pragma unroll
            for (int nt = 0; nt < 8; nt++) {
                int col0 = bn*128 + wn + nt*8 + 2*qk;
                float b0 = g.bias[col0], b1 = g.bias[col0+1];
                #pragma unroll
                for (int half = 0; half < 2; half++) {
                    int row = bm*128 + wm + mt*16 + qrow + 8*half;
                    float2 v;
                    v.x = d[mt][nt][2*half+0] + b0;
                    v.y = d[mt][nt][2*half+1] + b1;
                    *(float2*)&g.c[(size_t)row*DD + col0] = v;
                }
            }
    } else if (g.mode == 3) {
        // V: fp16 pack -> v16 [bh][s][k2]
        const int hg = bn*2 + (wn >> 6);
        #pragma unroll
        for (int mt = 0; mt < 2; mt++)
            #pragma unroll
            for (int half = 0; half < 2; half++) {
                const int row_g = bm*128 + wm + mt*16 + qrow + 8*half;
                const int b = row_g >> 11, s = row_g & (SS-1);
                const size_t base = ((size_t)(b*HH + hg)*SS + s)*32;
                #pragma unroll
                for (int nt = 0; nt < 8; nt++) {
                    const int col0 = bn*128 + wn + nt*8 + 2*qk;
                    float v0 = d[mt][nt][2*half+0] + g.bias[col0];
                    float v1 = d[mt][nt][2*half+1] + g.bias[col0+1];
                    g.o1[base + nt*4 + qk] = pack16(v0, v1);
                }
            }
    } else {
        // Q (mode 1) / K (mode 2): RoPE in registers
        const float scale = (g.mode == 1) ? 0.18033688011112042f : 1.0f;
        const int hg = bn*2 + (wn >> 6);
        #pragma unroll
        for (int mt = 0; mt < 2; mt++)
            #pragma unroll
            for (int half = 0; half < 2; half++) {
                const int row_g = bm*128 + wm + mt*16 + qrow + 8*half;
                const int b = row_g >> 11, s = row_g & (SS-1);
                const size_t base = ((size_t)(b*HH + hg)*SS + s)*32;
                #pragma unroll
                for (int nt = 0; nt < 4; nt++) {
                    const int col0 = bn*128 + wn + nt*8 + 2*qk;
                    const int j0 = nt*8 + 2*qk;
                    float x0 = d[mt][nt][2*half+0]   + g.bias[col0];
                    float x1 = d[mt][nt][2*half+1]   + g.bias[col0+1];
                    float y0 = d[mt][nt+4][2*half+0] + g.bias[col0+32];
                    float y1 = d[mt][nt+4][2*half+1] + g.bias[col0+33];
                    float c0 = cosT[s*32 + j0], c1 = cosT[s*32 + j0 + 1];
                    float s0 = sinT[s*32 + j0], s1 = sinT[s*32 + j0 + 1];
                    float o0 = (x0*c0 - y0*s0) * scale;
                    float o1 = (x1*c1 - y1*s1) * scale;
                    float p0 = (y0*c0 + x0*s0) * scale;
                    float p1 = (y1*c1 + x1*s1) * scale;
                    const int k2 = nt*4 + qk;
                    if (g.mode == 1) {
                        float r0, r1;
                        uint32_t hv = pack_hi16(o0, o1, r0, r1);
                        g.o1[base + k2] = hv;
                        g.o2[base + k2] = pack_lo16(r0, r1);
                        hv = pack_hi16(p0, p1, r0, r1);
                        g.o1[base + k2 + 16] = hv;
                        g.o2[base + k2 + 16] = pack_lo16(r0, r1);
                    } else {
                        g.o1[base + k2]      = pack16(o0, o1);
                        g.o1[base + k2 + 16] = pack16(p0, p1);
                    }
                }
            }
    }
}

// ---------------------------------------------------------------------------
// v_split2: pair adjacent key rows from v16 [bh][s][k2] (fp16) into
// vh[bh][kp][d] = half2(V[2kp][d], V[2kp+1][d]) via byte_perm.
// ---------------------------------------------------------------------------
__global__ __launch_bounds__(256) void v_split2(
    const uint32_t* __restrict__ v16, uint32_t* __restrict__ vh)
{
    const int t = blockIdx.x * 256 + threadIdx.x;
    const int d4 = (t & 15) * 4;          // d = d4..d4+3
    const int kp = (t >> 4) & 1023;
    const int bh = t >> 14;

    const uint32_t* rA = v16 + ((size_t)bh*SS + 2*kp)*32 + (d4 >> 1);
    const uint32_t* rB = rA + 32;
    uint2 a = *(const uint2*)rA;
    uint2 b = *(const uint2*)rB;

    uint4 o;
    o.x = __byte_perm(a.x, b.x, 0x5410);
    o.y = __byte_perm(a.x, b.x, 0x7632);
    o.z = __byte_perm(a.y, b.y, 0x5410);
    o.w = __byte_perm(a.y, b.y, 0x7632);

    size_t base = ((size_t)bh*1024 + kp)*64 + d4;
    *(uint4*)&vh[base] = o;
}

// ---------------------------------------------------------------------------
// Flash v6 (R15/R16 winner): fp16 2+2 passes, no-max softmax, cp.async K/V.
// ---------------------------------------------------------------------------
#define QP 36
#define VP 72
#define FLASH_SMEM (18432*4)

__global__ __launch_bounds__(256, 2) void flash_tc6(
    const uint32_t* __restrict__ qh_g, const uint32_t* __restrict__ ql_g,
    const uint32_t* __restrict__ kh_g, const uint32_t* __restrict__ vh_g,
    uint32_t* __restrict__ cth, uint32_t* __restrict__ ctl)
{
    extern __shared__ uint32_t smu[];
    const uint32_t sbase = (uint32_t)__cvta_generic_to_shared(smu);

    const int tid = threadIdx.x;
    const int qi = 15 - blockIdx.x;
    const int bh = blockIdx.y;
    const int b = bh >> 4, h = bh & 15;
    const int lane = tid & 31, wid = tid >> 5;
    const int qk = lane & 3, qrow = lane >> 2;
    const int wr = wid * 16;
    const int nkt = 2*qi + 2;

    const int krow = tid >> 2, kk2b = (tid & 3) * 8;
    const int vkp  = tid >> 3, vdb  = (tid & 7) * 8;
    const size_t kgo = ((size_t)bh*SS + krow)*32 + kk2b;
    const size_t vgo = ((size_t)bh*1024 + vkp)*64 + vdb;

    {
        const int row = tid >> 1, cb = (tid & 1) * 16;
        const uint32_t* sh = qh_g + ((size_t)bh*SS + qi*128 + row)*32 + cb;
        const uint32_t* sl = ql_g + ((size_t)bh*SS + qi*128 + row)*32 + cb;
        uint32_t dh = sbase + (row*QP + cb)*4;
        uint32_t dl = sbase + (4608 + row*QP + cb)*4;
        CPA16(dh,    sh);     CPA16(dh+16, sh+4);
        CPA16(dh+32, sh+8);   CPA16(dh+48, sh+12);
        CPA16(dl,    sl);     CPA16(dl+16, sl+4);
        CPA16(dl+32, sl+8);   CPA16(dl+48, sl+12);
    }
    CPA_COMMIT();

    #pragma unroll
    for (int pk = 0; pk < 2; pk++) {
        uint32_t kh_d = sbase + (9216  + pk*2304 + krow*QP + kk2b)*4;
        uint32_t vh_d = sbase + (13824 + pk*2304 + vkp*VP + vdb)*4;
        const uint32_t* skh = kh_g + kgo + (size_t)pk*64*32;
        const uint32_t* svh = vh_g + vgo + (size_t)pk*32*64;
        CPA16(kh_d, skh);  CPA16(kh_d+16, skh+4);
        CPA16(vh_d, svh);  CPA16(vh_d+16, svh+4);
        CPA_COMMIT();
    }

    float l0 = 0.f, l1 = 0.f;
    float of[8][4];
    #pragma unroll
    for (int nt = 0; nt < 8; nt++)
        #pragma unroll
        for (int i = 0; i < 4; i++) of[nt][i] = 0.f;

    const uint32_t* QhS = smu;
    const uint32_t* QlS = smu + 4608;

    for (int kt = 0; kt < nkt; kt++) {
        const int st = kt & 1;
        if (kt + 1 < nkt) { CPA_WAIT(1); } else { CPA_WAIT(0); }
        __syncthreads();

        const uint32_t* KhS = smu + 9216  + st*2304;
        const uint32_t* VhS = smu + 13824 + st*2304;

        float sf[8][4];
        #pragma unroll
        for (int nt = 0; nt < 8; nt++)
            #pragma unroll
            for (int i = 0; i < 4; i++) sf[nt][i] = 0.f;

        #pragma unroll
        for (int kc = 0; kc < 4; kc++) {
            uint32_t ah[4], al[4];
            const int k2a = qk + 8*kc, k2c = k2a + 4;
            const int r0o = (wr + qrow)*QP, r1o = (wr + qrow + 8)*QP;
            ah[0] = QhS[r0o + k2a]; ah[1] = QhS[r1o + k2a];
            ah[2] = QhS[r0o + k2c]; ah[3] = QhS[r1o + k2c];
            al[0] = QlS[r0o + k2a]; al[1] = QlS[r1o + k2a];
            al[2] = QlS[r0o + k2c]; al[3] = QlS[r1o + k2c];
            #pragma unroll
            for (int nt = 0; nt < 8; nt++) {
                const int co = (nt*8 + qrow)*QP;
                uint32_t bb[2] = { KhS[co + k2a], KhS[co + k2c] };
                MMA_F16(sf[nt], ah, bb);
            }
            #pragma unroll
            for (int nt = 0; nt < 8; nt++) {
                const int co = (nt*8 + qrow)*QP;
                uint32_t bb[2] = { KhS[co + k2a], KhS[co + k2c] };
                MMA_F16(sf[nt], al, bb);
            }
        }

        if (kt >= 2*qi) {
            #pragma unroll
            for (int nt = 0; nt < 8; nt++) {
                #pragma unroll
                for (int i = 0; i < 4; i++) {
                    int col_g = kt*64 + nt*8 + 2*qk + (i & 1);
                    int row_g = qi*128 + wr + qrow + 8*(i >> 1);
                    if (col_g > row_g) sf[nt][i] = -1e30f;
                }
            }
        }

        #pragma unroll
        for (int nt = 0; nt < 8; nt++) {
            sf[nt][0] = ex2(sf[nt][0]);
            sf[nt][1] = ex2(sf[nt][1]);
            sf[nt][2] = ex2(sf[nt][2]);
            sf[nt][3] = ex2(sf[nt][3]);
            l0 += sf[nt][0] + sf[nt][1];
            l1 += sf[nt][2] + sf[nt][3];
        }

        #pragma unroll
        for (int kc = 0; kc < 4; kc++) {
            uint32_t pah[4], pal[4];
            float r0, r1;
            pah[0] = pack_hi16(sf[2*kc][0],   sf[2*kc][1],   r0, r1); pal[0] = pack_lo16(r0, r1);
            pah[1] = pack_hi16(sf[2*kc][2],   sf[2*kc][3],   r0, r1); pal[1] = pack_lo16(r0, r1);
            pah[2] = pack_hi16(sf[2*kc+1][0], sf[2*kc+1][1], r0, r1); pal[2] = pack_lo16(r0, r1);
            pah[3] = pack_hi16(sf[2*kc+1][2], sf[2*kc+1][3], r0, r1); pal[3] = pack_lo16(r0, r1);
            const int kpa = 8*kc + qk, kpc = kpa + 4;
            #pragma unroll
            for (int nt = 0; nt < 8; nt++) {
                const int col = nt*8 + qrow;
                uint32_t bb[2] = { VhS[kpa*VP + col], VhS[kpc*VP + col] };
                MMA_F16(of[nt], pah, bb);
            }
            #pragma unroll
            for (int nt = 0; nt < 8; nt++) {
                const int col = nt*8 + qrow;
                uint32_t bb[2] = { VhS[kpa*VP + col], VhS[kpc*VP + col] };
                MMA_F16(of[nt], pal, bb);
            }
        }

        __syncthreads();

        if (kt + 2 < nkt) {
            const int nk = kt + 2;
            uint32_t kh_d = sbase + (9216  + st*2304 + krow*QP + kk2b)*4;
            uint32_t vh_d = sbase + (13824 + st*2304 + vkp*VP + vdb)*4;
            const uint32_t* skh = kh_g + kgo + (size_t)nk*64*32;
            const uint32_t* svh = vh_g + vgo + (size_t)nk*32*64;
            CPA16(kh_d, skh);  CPA16(kh_d+16, skh+4);
            CPA16(vh_d, svh);  CPA16(vh_d+16, svh+4);
            CPA_COMMIT();
        }
    }

    l0 += __shfl_xor_sync(0xffffffffu, l0, 1);
    l0 += __shfl_xor_sync(0xffffffffu, l0, 2);
    l1 += __shfl_xor_sync(0xffffffffu, l1, 1);
    l1 += __shfl_xor_sync(0xffffffffu, l1, 2);

    float inv0 = 1.f / l0, inv1 = 1.f / l1;
    #pragma unroll
    for (int nt = 0; nt < 8; nt++) {
        const int k2g = h*32 + nt*4 + qk;
        const int chn = k2g >> 3, wix = k2g & 7;
        const int row0 = b*SS + qi*128 + wr + qrow;
        float r0, r1;
        uint32_t hv = pack_hi16(of[nt][0]*inv0, of[nt][1]*inv0, r0, r1);
        size_t di = ((size_t)chn*MROWS + row0)*8 + wix;
        cth[di] = hv;
        ctl[di] = pack_lo16(r0, r1);
        hv = pack_hi16(of[nt][2]*inv1, of[nt][3]*inv1, r0, r1);
        di = ((size_t)chn*MROWS + row0 + 8)*8 + wix;
        cth[di] = hv;
        ctl[di] = pack_lo16(r0, r1);
    }
}

// ---------------------------------------------------------------------------
extern "C" void kernel_launch(void* const* d_in, const int* in_sizes, int n_in,
                              void* d_out, int out_size)
{
    (void)in_sizes; (void)n_in; (void)out_size;
    const float* query = (const float*)d_in[0];
    const float* key   = (const float*)d_in[1];
    const float* value = (const float*)d_in[2];
    const float* Wq = (const float*)d_in[4];
    const float* bq = (const float*)d_in[5];
    const float* Wk = (const float*)d_in[6];
    const float* bk = (const float*)d_in[7];
    const float* Wv = (const float*)d_in[8];
    const float* bv = (const float*)d_in[9];
    const float* Wo = (const float*)d_in[10];
    const float* bo = (const float*)d_in[11];
    float* out = (float*)d_out;

    float *cosT, *sinT;
    uint32_t *qh, *ql, *kh, *v16, *vh;
    uint32_t *ah, *al, *wh, *cth, *ctl;
    cudaGetSymbolAddress((void**)&cosT, g_cos);
    cudaGetSymbolAddress((void**)&sinT, g_sin);
    cudaGetSymbolAddress((void**)&qh, g_qh);
    cudaGetSymbolAddress((void**)&ql, g_ql);
    cudaGetSymbolAddress((void**)&kh, g_kh);
    cudaGetSymbolAddress((void**)&v16, g_v16);
    cudaGetSymbolAddress((void**)&vh, g_vh);
    cudaGetSymbolAddress((void**)&ah, g_ah);
    cudaGetSymbolAddress((void**)&al, g_al);
    cudaGetSymbolAddress((void**)&wh, g_wh);
    cudaGetSymbolAddress((void**)&cth, g_cth);
    cudaGetSymbolAddress((void**)&ctl, g_ctl);

    const size_t ASTRIDE = (size_t)MROWS*512;
    const size_t WSTRIDE = (size_t)DD*512;

    cudaFuncSetAttribute(flash_tc6, cudaFuncAttributeMaxDynamicSharedMemorySize, FLASH_SMEM);
    cudaFuncSetAttribute(gemm_fp16b, cudaFuncAttributeMaxDynamicSharedMemorySize, GEMM_SMEM);

    rope_tables<<<SS*32/256, 256>>>(cosT, sinT);

    const int ABLK = MROWS*DD/8/256;   // 2048
    const int WBLK = DD*DD/8/256;      // 512
    dim3 sp3Grid(ABLK, 3);
    split_act3<<<sp3Grid, 256>>>(query, key, value, ah, al, ASTRIDE);
    dim3 sp4Grid(WBLK, 4);
    split_w4<<<sp4Grid, 256>>>(Wq, Wk, Wv, Wo, wh, WSTRIDE);

    // Fused QKV GEMM with RoPE/pack epilogues
    GArg gq = { ah + 0*ASTRIDE, al + 0*ASTRIDE, wh + 0*WSTRIDE, bq, nullptr, qh, ql, 1 };
    GArg gk = { ah + 1*ASTRIDE, al + 1*ASTRIDE, wh + 1*WSTRIDE, bk, nullptr, kh, nullptr, 2 };
    GArg gv = { ah + 2*ASTRIDE, al + 2*ASTRIDE, wh + 2*WSTRIDE, bv, nullptr, v16, nullptr, 3 };
    dim3 gemmGrid(DD/128, MROWS/128, 3);
    gemm_fp16b<<<gemmGrid, 256, GEMM_SMEM>>>(gq, gk, gv, cosT, sinT);

    v_split2<<<(BB*HH*1024*16)/256, 256>>>(v16, vh);

    dim3 faGrid(SS/128, BB*HH);            // (16, 32)
    flash_tc6<<<faGrid, 256, FLASH_SMEM>>>(qh, ql, kh, vh, cth, ctl);

    GArg go = { cth, ctl, wh + 3*WSTRIDE, bo, out, nullptr, nullptr, 0 };
    dim3 gemmGridO(DD/128, MROWS/128, 1);
    gemm_fp16b<<<gemmGridO, 256, GEMM_SMEM>>>(go, go, go, cosT, sinT);
}